// round 14
// baseline (speedup 1.0000x reference)
#include <cuda_runtime.h>
#include <cuda_fp16.h>
#include <cstdint>

// ---------------------------------------------------------------------------
// SparseMultiHeadAttention  B=2 S=2048 D=1024 H=16 hd=64  top-k k=409
// R13: R12 base + two-stream scores||select pipeline (4 heads/chunk)
// ---------------------------------------------------------------------------

#define Bb   2
#define Ss   2048
#define Dd   1024
#define Hh   16
#define HD   64
#define BH   (Bb*Hh)          // 32
#define NROWS (Bb*Hh*Ss)      // 65536
#define KSEL 409
#define PAD  512
#define CH_BH   4             // heads per pipeline chunk
#define NCHUNK  (BH/CH_BH)    // 8

// scratch (device globals: allocation-free)
__device__ float  g_Q[(size_t)BH*Ss*HD];
__device__ float  g_K[(size_t)BH*Ss*HD];
__device__ __half g_Vh[(size_t)BH*Ss*HD];
__device__ float  g_HO[(size_t)Bb*Ss*Dd];             // head_out (B,S,H,hd)
__device__ float  g_scores[(size_t)NROWS*Ss];         // 512 MB
__device__ int2   g_ip[(size_t)NROWS*PAD];            // (idx, p-bits)
__device__ int    g_cnt[NROWS];

// ---------------------------------------------------------------------------
// packed f32x2 helpers
// ---------------------------------------------------------------------------
typedef unsigned long long u64t;

__device__ __forceinline__ u64t pack2(float x, float y) {
    u64t r;
    asm("mov.b64 %0, {%1, %2};" : "=l"(r) : "f"(x), "f"(y));
    return r;
}
__device__ __forceinline__ void fma2(u64t& d, u64t a, u64t b) {
    asm("fma.rn.f32x2 %0, %1, %2, %0;" : "+l"(d) : "l"(a), "l"(b));
}
__device__ __forceinline__ float2 unpack2(u64t v) {
    float2 f;
    asm("mov.b64 {%0, %1}, %2;" : "=f"(f.x), "=f"(f.y) : "l"(v));
    return f;
}

// ---------------------------------------------------------------------------
// shared 128x128x(K=1024) mainloop for the projection GEMMs
// ---------------------------------------------------------------------------
__device__ __forceinline__ void proj_mainloop(const float* __restrict__ A,
                                              const float* __restrict__ W,
                                              float (*As)[132], float (*Ws)[132],
                                              int m0, int n0, int tid,
                                              u64t acc[8][4])
{
    int tx = tid & 15, ty = tid >> 4;
#pragma unroll
    for (int i = 0; i < 8; i++)
#pragma unroll
        for (int j = 0; j < 4; j++) acc[i][j] = 0ull;

    for (int kt = 0; kt < Dd; kt += 32) {
#pragma unroll
        for (int l = 0; l < 4; l++) {
            int fid = tid + 256 * l;
            int lm = fid >> 3;
            int lk = (fid & 7) * 4;
            float4 av = *(const float4*)(A + (size_t)(m0 + lm) * Dd + kt + lk);
            As[lk+0][lm] = av.x; As[lk+1][lm] = av.y;
            As[lk+2][lm] = av.z; As[lk+3][lm] = av.w;
            float4 wv = *(const float4*)(W + (size_t)(n0 + lm) * Dd + kt + lk);
            Ws[lk+0][lm] = wv.x; Ws[lk+1][lm] = wv.y;
            Ws[lk+2][lm] = wv.z; Ws[lk+3][lm] = wv.w;
        }
        __syncthreads();
#pragma unroll
        for (int kk = 0; kk < 32; kk++) {
            float4 a0 = *(const float4*)&As[kk][ty*8];
            float4 a1 = *(const float4*)&As[kk][ty*8+4];
            ulonglong2 bq0 = *(const ulonglong2*)&Ws[kk][tx*8];
            ulonglong2 bq1 = *(const ulonglong2*)&Ws[kk][tx*8+4];
            u64t bp[4] = {bq0.x, bq0.y, bq1.x, bq1.y};
            float a[8] = {a0.x,a0.y,a0.z,a0.w,a1.x,a1.y,a1.z,a1.w};
#pragma unroll
            for (int i = 0; i < 8; i++) {
                u64t ai = pack2(a[i], a[i]);
#pragma unroll
                for (int j = 0; j < 4; j++) fma2(acc[i][j], ai, bp[j]);
            }
        }
        __syncthreads();
    }
}

// ---------------------------------------------------------------------------
// K1: fused QKV projection.  z = 0:Q  1:K  2:V(->half)
// ---------------------------------------------------------------------------
__global__ __launch_bounds__(256)
void qkv_kernel(const float* __restrict__ x,
                const float* __restrict__ Wq, const float* __restrict__ bq,
                const float* __restrict__ Wk, const float* __restrict__ bk,
                const float* __restrict__ Wv, const float* __restrict__ bv)
{
    __shared__ __align__(16) float As[32][132];
    __shared__ __align__(16) float Ws[32][132];

    int mode = blockIdx.z;
    const float* W    = (mode == 0) ? Wq : (mode == 1) ? Wk : Wv;
    const float* bias = (mode == 0) ? bq : (mode == 1) ? bk : bv;

    int n0 = blockIdx.x * 128;
    int m0 = blockIdx.y * 128;
    int tid = threadIdx.x;
    int tx = tid & 15, ty = tid >> 4;

    u64t acc[8][4];
    proj_mainloop(x, W, As, Ws, m0, n0, tid, acc);

    int nb = n0 + tx*8;
    float4 bs0 = *(const float4*)(bias + nb);
    float4 bs1 = *(const float4*)(bias + nb + 4);
    float bv8[8] = {bs0.x,bs0.y,bs0.z,bs0.w,bs1.x,bs1.y,bs1.z,bs1.w};

#pragma unroll
    for (int i = 0; i < 8; i++) {
        int m = m0 + ty*8 + i;
        float v[8];
#pragma unroll
        for (int j = 0; j < 4; j++) {
            float2 f = unpack2(acc[i][j]);
            v[2*j]   = f.x + bv8[2*j];
            v[2*j+1] = f.y + bv8[2*j+1];
        }
        int b = m >> 11, s = m & (Ss-1);
        int h = nb >> 6, d = nb & (HD-1);
        size_t off = (((size_t)(b*Hh + h)) * Ss + s) * HD + d;
        if (mode == 2) {
            __half2* p = (__half2*)g_Vh + (off >> 1);
            p[0] = __floats2half2_rn(v[0],v[1]);
            p[1] = __floats2half2_rn(v[2],v[3]);
            p[2] = __floats2half2_rn(v[4],v[5]);
            p[3] = __floats2half2_rn(v[6],v[7]);
        } else {
            float* dst = (mode == 0) ? g_Q : g_K;
            float4* p = (float4*)(dst + off);
            p[0] = make_float4(v[0],v[1],v[2],v[3]);
            p[1] = make_float4(v[4],v[5],v[6],v[7]);
        }
    }
}

// ---------------------------------------------------------------------------
// K6: output projection  out = g_HO @ Wo^T + bo
// ---------------------------------------------------------------------------
__global__ __launch_bounds__(256)
void oproj_kernel(const float* __restrict__ Wo, const float* __restrict__ bo,
                  float* __restrict__ Cext)
{
    __shared__ __align__(16) float As[32][132];
    __shared__ __align__(16) float Ws[32][132];

    int n0 = blockIdx.x * 128;
    int m0 = blockIdx.y * 128;
    int tid = threadIdx.x;
    int tx = tid & 15, ty = tid >> 4;

    u64t acc[8][4];
    proj_mainloop((const float*)g_HO, Wo, As, Ws, m0, n0, tid, acc);

    int nb = n0 + tx*8;
    float4 bs0 = *(const float4*)(bo + nb);
    float4 bs1 = *(const float4*)(bo + nb + 4);
    float bv8[8] = {bs0.x,bs0.y,bs0.z,bs0.w,bs1.x,bs1.y,bs1.z,bs1.w};

#pragma unroll
    for (int i = 0; i < 8; i++) {
        int m = m0 + ty*8 + i;
        float v[8];
#pragma unroll
        for (int j = 0; j < 4; j++) {
            float2 f = unpack2(acc[i][j]);
            v[2*j]   = f.x + bv8[2*j];
            v[2*j+1] = f.y + bv8[2*j+1];
        }
        float4* p = (float4*)(Cext + (size_t)m * Dd + nb);
        p[0] = make_float4(v[0],v[1],v[2],v[3]);
        p[1] = make_float4(v[4],v[5],v[6],v[7]);
    }
}

// ---------------------------------------------------------------------------
// K2: scores[bh,q,k] for bh in [bh0, bh0+CH_BH)
// ---------------------------------------------------------------------------
__global__ __launch_bounds__(256)
void scores_kernel(const float* __restrict__ temperature, int bh0)
{
    extern __shared__ __align__(16) float sm[];
    float (*Qs)[132] = (float(*)[132])sm;
    float (*Ks)[132] = (float(*)[132])(sm + 64*132);

    int bh = bh0 + blockIdx.z;
    int h  = bh & (Hh-1);
    float t = temperature[h];
    t = (t < 0.1f) ? 0.1f : t;
    float sc = 0.125f / t;

    int q0 = blockIdx.y * 128;
    int k0 = blockIdx.x * 128;
    int tid = threadIdx.x;
    int tx = tid & 15, ty = tid >> 4;

    const float* Qb = g_Q + (size_t)bh * Ss * HD;
    const float* Kb = g_K + (size_t)bh * Ss * HD;

#pragma unroll
    for (int l = 0; l < 8; l++) {
        int fid = tid + 256 * l;
        int lm = fid >> 4;
        int lk = (fid & 15) * 4;
        float4 v = *(const float4*)(Qb + (size_t)(q0 + lm) * HD + lk);
        Qs[lk+0][lm] = v.x; Qs[lk+1][lm] = v.y; Qs[lk+2][lm] = v.z; Qs[lk+3][lm] = v.w;
        float4 w = *(const float4*)(Kb + (size_t)(k0 + lm) * HD + lk);
        Ks[lk+0][lm] = w.x; Ks[lk+1][lm] = w.y; Ks[lk+2][lm] = w.z; Ks[lk+3][lm] = w.w;
    }
    __syncthreads();

    u64t acc[8][4];
#pragma unroll
    for (int i = 0; i < 8; i++)
#pragma unroll
        for (int j = 0; j < 4; j++) acc[i][j] = 0ull;

#pragma unroll
    for (int kk = 0; kk < 64; kk++) {
        float4 a0 = *(const float4*)&Qs[kk][ty*8];
        float4 a1 = *(const float4*)&Qs[kk][ty*8+4];
        ulonglong2 bq0 = *(const ulonglong2*)&Ks[kk][tx*8];
        ulonglong2 bq1 = *(const ulonglong2*)&Ks[kk][tx*8+4];
        u64t bp[4] = {bq0.x, bq0.y, bq1.x, bq1.y};
        float a[8] = {a0.x,a0.y,a0.z,a0.w,a1.x,a1.y,a1.z,a1.w};
#pragma unroll
        for (int i = 0; i < 8; i++) {
            u64t ai = pack2(a[i], a[i]);
#pragma unroll
            for (int j = 0; j < 4; j++) fma2(acc[i][j], ai, bp[j]);
        }
    }

#pragma unroll
    for (int i = 0; i < 8; i++) {
        size_t rowoff = ((size_t)bh * Ss + (q0 + ty*8 + i)) * Ss + k0 + tx*8;
        float4* p = (float4*)(g_scores + rowoff);
        float2 f0 = unpack2(acc[i][0]);
        float2 f1 = unpack2(acc[i][1]);
        float2 f2 = unpack2(acc[i][2]);
        float2 f3 = unpack2(acc[i][3]);
        p[0] = make_float4(f0.x*sc, f0.y*sc, f1.x*sc, f1.y*sc);
        p[1] = make_float4(f2.x*sc, f2.y*sc, f3.x*sc, f3.y*sc);
    }
}

// ---------------------------------------------------------------------------
// K3: fused select + headout (R12 version, row offset param).
// ---------------------------------------------------------------------------
__device__ __forceinline__ float key_decode(unsigned uu) {
    unsigned b = (uu & 0x80000000u) ? (uu & 0x7FFFFFFFu) : ~uu;
    return __uint_as_float(b);
}
__device__ __forceinline__ unsigned hget(const unsigned* histw, int b) {
    return (histw[b >> 1] >> ((b & 1) * 16)) & 0xFFFFu;
}

template <int NBINS>
__device__ __forceinline__ void find_kth_p(const unsigned* histw, int k,
                                           unsigned* wtot,
                                           volatile int* s_bin, volatile int* s_rem)
{
    const int PER = NBINS / 256;
    int tid = threadIdx.x, lane = tid & 31, wp = tid >> 5;
    int base = NBINS - PER * (tid + 1);

    unsigned csum = 0;
    int wbase = base >> 1;
#pragma unroll
    for (int i = 0; i < PER/2; i++) {
        unsigned w = histw[wbase + i];
        csum += (w & 0xFFFFu) + (w >> 16);
    }
    unsigned inc = csum;
#pragma unroll
    for (int off = 1; off < 32; off <<= 1) {
        unsigned n = __shfl_up_sync(0xffffffffu, inc, off);
        if (lane >= off) inc += n;
    }
    if (lane == 31) wtot[wp] = inc;
    __syncthreads();
    unsigned woff = 0;
#pragma unroll
    for (int w = 0; w < 8; w++) woff += (w < wp) ? wtot[w] : 0u;
    inc += woff;
    unsigned pre = inc - csum;
    if (pre < (unsigned)k && (unsigned)k <= inc) {
        unsigned acc = pre;
        for (int b = base + PER - 1; b >= base; b--) {
            unsigned c = hget(histw, b);
            if (acc + c >= (unsigned)k) { *s_bin = b; *s_rem = k - (int)acc; break; }
            acc += c;
        }
    }
    __syncthreads();
}

__global__ __launch_bounds__(256)
void select_kernel(int row0)
{
    __shared__ unsigned u[Ss];
    __shared__ int2     sbuf[Ss];
    __shared__ unsigned histw[2048];
    __shared__ unsigned wtot[8];
    __shared__ float    wred[8];
    __shared__ int      s_bin, s_rem;
    __shared__ unsigned s_cand, s_cand2, s_out, s_umax;

    unsigned* cand  = (unsigned*)sbuf;
    unsigned* cand2 = (unsigned*)sbuf + 2048;

    int row = row0 + blockIdx.x;
    int tid = threadIdx.x;
    int lane = tid & 31;
    int wp = tid >> 5;
    unsigned lml = (1u << lane) - 1u;

    const float4* src4 = (const float4*)(g_scores + (size_t)row * Ss);

#pragma unroll
    for (int l = 0; l < 8; l++) histw[tid + 256*l] = 0;
    if (tid == 0) { s_cand = 0; s_cand2 = 0; s_out = 0; s_umax = 0; }
    __syncthreads();

    unsigned umax = 0;
#pragma unroll
    for (int l = 0; l < 2; l++) {
        int i4 = tid + 256 * l;
        float4 v = src4[i4];
        float f[4] = {v.x, v.y, v.z, v.w};
#pragma unroll
        for (int c = 0; c < 4; c++) {
            unsigned bts = __float_as_uint(f[c]);
            unsigned uu = (bts & 0x80000000u) ? ~bts : (bts | 0x80000000u);
            u[i4*4 + c] = uu;
            umax = max(umax, uu);
            unsigned bin = uu >> 20;
            atomicAdd(&histw[bin >> 1], 1u << ((bin & 1) * 16));
        }
    }
#pragma unroll
    for (int off = 16; off; off >>= 1)
        umax = max(umax, __shfl_xor_sync(0xffffffffu, umax, off));
    if (lane == 0) atomicMax(&s_umax, umax);
    __syncthreads();

    find_kth_p<4096>(histw, KSEL, wtot, &s_bin, &s_rem);
    int bin1 = s_bin, rem1 = s_rem;

#pragma unroll
    for (int l = 0; l < 8; l++) {
        unsigned uu = u[tid + 256*l];
        if ((uu >> 20) == (unsigned)bin1)
            cand[atomicAdd(&s_cand, 1u)] = uu;
    }
    __syncthreads();
    int c1 = (int)s_cand;

    if (tid < 256) { histw[tid] = 0; histw[tid + 256] = 0; }
    __syncthreads();
    for (int j = tid; j < c1; j += 256) {
        unsigned bin = (cand[j] >> 10) & 0x3FFu;
        atomicAdd(&histw[bin >> 1], 1u << ((bin & 1) * 16));
    }
    __syncthreads();
    find_kth_p<1024>(histw, rem1, wtot, &s_bin, &s_rem);
    int bin2 = s_bin, rem2 = s_rem;

    for (int j = tid; j < c1; j += 256) {
        unsigned uu = cand[j];
        if (((uu >> 10) & 0x3FFu) == (unsigned)bin2)
            cand2[atomicAdd(&s_cand2, 1u)] = uu;
    }
    __syncthreads();
    int c2 = (int)s_cand2;

    if (tid < 256) { histw[tid] = 0; histw[tid + 256] = 0; }
    __syncthreads();
    for (int j = tid; j < c2; j += 256) {
        unsigned bin = cand2[j] & 0x3FFu;
        atomicAdd(&histw[bin >> 1], 1u << ((bin & 1) * 16));
    }
    __syncthreads();
    find_kth_p<1024>(histw, rem2, wtot, &s_bin, &s_rem);
    unsigned thr = ((unsigned)bin1 << 20) | ((unsigned)bin2 << 10) | (unsigned)s_bin;

    float mx = key_decode(s_umax);

    float lsum = 0.f;
#pragma unroll
    for (int l = 0; l < 8; l++) {
        int i = tid + 256*l;
        unsigned uu = u[i];
        bool p = (uu >= thr);
        float e = p ? __expf(key_decode(uu) - mx) : 0.f;
        lsum += e;
        unsigned m = __ballot_sync(0xffffffffu, p);
        if (p) {
            int leader = __ffs(m) - 1;
            unsigned base;
            if (lane == leader) base = atomicAdd(&s_out, (unsigned)__popc(m));
            base = __shfl_sync(m, base, leader);
            sbuf[base + __popc(m & lml)] = make_int2(i, __float_as_int(e));
        }
    }
#pragma unroll
    for (int off = 16; off; off >>= 1)
        lsum += __shfl_xor_sync(0xffffffffu, lsum, off);
    if (lane == 0) wred[wp] = lsum;
    __syncthreads();

    float tot = 0.f;
#pragma unroll
    for (int w = 0; w < 8; w++) tot += wred[w];
    float inv = 1.0f / tot;

    int cnt = (int)min(s_out, (unsigned)PAD);
    int2* gip = g_ip + (size_t)row * PAD;
    for (int j = tid; j < cnt; j += 256) {
        int2 e = sbuf[j];
        gip[j] = make_int2(e.x, __float_as_int(__int_as_float(e.y) * inv));
    }
    if (tid == 0) g_cnt[row] = cnt;

    // fused headout
    {
        float (*pbuf)[64] = (float(*)[64])histw;
        int bh = row >> 11;
        const char* Vb = (const char*)(g_Vh + (size_t)bh * Ss * HD);
        int ksel = lane >> 3;
        int dgrp = lane & 7;

        float acc[8];
#pragma unroll
        for (int d = 0; d < 8; d++) acc[d] = 0.f;

        for (int j0 = wp * 4; j0 < cnt; j0 += 32) {
            int j = j0 + ksel;
            int idx = 0; float p = 0.f;
            if (j < cnt) { int2 ip = sbuf[j]; idx = ip.x; p = __int_as_float(ip.y) * inv; }
            uint4 v = *(const uint4*)(Vb + ((size_t)idx << 7) + (dgrp << 4));
            const __half2* hv = (const __half2*)&v;
#pragma unroll
            for (int c = 0; c < 4; c++) {
                float2 f = __half22float2(hv[c]);
                acc[2*c]   += p * f.x;
                acc[2*c+1] += p * f.y;
            }
        }

#pragma unroll
        for (int d = 0; d < 8; d++) {
            acc[d] += __shfl_xor_sync(0xffffffffu, acc[d], 8);
            acc[d] += __shfl_xor_sync(0xffffffffu, acc[d], 16);
        }
        if (lane < 8) {
#pragma unroll
            for (int d = 0; d < 8; d++) pbuf[wp][dgrp*8 + d] = acc[d];
        }
        __syncthreads();

        if (tid < 64) {
            float s = 0.f;
#pragma unroll
            for (int gg = 0; gg < 8; gg++) s += pbuf[gg][tid];
            int b = bh >> 4, h = bh & 15, sq = row & (Ss-1);
            g_HO[(((size_t)(b * Ss + sq)) * Hh + h) * HD + tid] = s;
        }
    }
}

// ---------------------------------------------------------------------------
// K5: avg_attention[b,q,:] = (1/H) * sum_h attn[b,h,q,:]
// ---------------------------------------------------------------------------
__global__ __launch_bounds__(256)
void avg_kernel(float* __restrict__ out_avg)
{
    __shared__ float acc[Ss];
    int bq = blockIdx.x;
    int b = bq >> 11, q = bq & (Ss-1);
    int tid = threadIdx.x;

    for (int i = tid; i < Ss; i += 256) acc[i] = 0.f;
    __syncthreads();

    const float invH = 1.0f / (float)Hh;
    for (int h = 0; h < Hh; h++) {
        int row = ((b * Hh + h) << 11) + q;
        int cnt = g_cnt[row];
        const int2* ip = g_ip + (size_t)row * PAD;
        for (int j = tid; j < cnt; j += 256) {
            int2 e = ip[j];
            atomicAdd(&acc[e.x], __int_as_float(e.y) * invH);
        }
    }
    __syncthreads();

    float* dst = out_avg + (size_t)bq * Ss;
    for (int i = tid; i < Ss; i += 256) dst[i] = acc[i];
}

// ---------------------------------------------------------------------------
extern "C" void kernel_launch(void* const* d_in, const int* in_sizes, int n_in,
                              void* d_out, int out_size)
{
    const float* x    = (const float*)d_in[0];
    const float* Wq   = (const float*)d_in[1];
    const float* bq   = (const float*)d_in[2];
    const float* Wk   = (const float*)d_in[3];
    const float* bk   = (const float*)d_in[4];
    const float* Wv   = (const float*)d_in[5];
    const float* bv   = (const float*)d_in[6];
    const float* Wo   = (const float*)d_in[7];
    const float* bo   = (const float*)d_in[8];
    const float* temp = (const float*)d_in[9];

    float* out     = (float*)d_out;
    float* out_avg = out + (size_t)Bb * Ss * Dd;

    static cudaStream_t sB = nullptr;
    static cudaEvent_t ev_sc[NCHUNK];
    static cudaEvent_t ev_sel_last = nullptr, ev_join = nullptr;
    if (sB == nullptr) {
        cudaStreamCreateWithFlags(&sB, cudaStreamNonBlocking);
        for (int c = 0; c < NCHUNK; c++)
            cudaEventCreateWithFlags(&ev_sc[c], cudaEventDisableTiming);
        cudaEventCreateWithFlags(&ev_sel_last, cudaEventDisableTiming);
        cudaEventCreateWithFlags(&ev_join, cudaEventDisableTiming);
        cudaFuncSetAttribute(scores_kernel,
                             cudaFuncAttributeMaxDynamicSharedMemorySize,
                             2 * 64 * 132 * 4);
    }

    const int ROWS_PER_CHUNK = CH_BH * Ss;        // 8192

    // stream A (default 0): qkv -> scores chunks -> avg
    dim3 gqkv(Dd / 128, (Bb * Ss) / 128, 3);      // (8, 32, 3)
    qkv_kernel<<<gqkv, 256>>>(x, Wq, bq, Wk, bk, Wv, bv);

    dim3 gsc(Ss / 128, Ss / 128, CH_BH);          // (16, 16, 4)
    for (int c = 0; c < NCHUNK; c++) {
        scores_kernel<<<gsc, 256, 2 * 64 * 132 * 4>>>(temp, c * CH_BH);
        cudaEventRecord(ev_sc[c], 0);
        // stream B: select chunk c after its scores are done
        cudaStreamWaitEvent(sB, ev_sc[c], 0);
        select_kernel<<<ROWS_PER_CHUNK, 256, 0, sB>>>(c * ROWS_PER_CHUNK);
    }
    cudaEventRecord(ev_sel_last, sB);

    // stream B continues with oproj (needs all g_HO from selects)
    dim3 gproj(Dd / 128, (Bb * Ss) / 128);        // (8, 32)
    oproj_kernel<<<gproj, 256, 0, sB>>>(Wo, bo, out);
    cudaEventRecord(ev_join, sB);

    // stream A: avg needs all selects' g_ip/g_cnt
    cudaStreamWaitEvent(0, ev_sel_last, 0);
    avg_kernel<<<Bb * Ss, 256>>>(out_avg);

    // join streams before returning
    cudaStreamWaitEvent(0, ev_join, 0);
}

// round 15
// speedup vs baseline: 1.0414x; 1.0414x over previous
#include <cuda_runtime.h>
#include <cuda_fp16.h>
#include <cstdint>

// ---------------------------------------------------------------------------
// SparseMultiHeadAttention  B=2 S=2048 D=1024 H=16 hd=64  top-k k=409
// R14: R12 base + select: direct rank-scan kth (skip radix L2/L3), gather x2
// ---------------------------------------------------------------------------

#define Bb   2
#define Ss   2048
#define Dd   1024
#define Hh   16
#define HD   64
#define BH   (Bb*Hh)          // 32
#define NROWS (Bb*Hh*Ss)      // 65536
#define KSEL 409
#define PAD  512

// scratch (device globals: allocation-free)
__device__ float  g_Q[(size_t)BH*Ss*HD];
__device__ float  g_K[(size_t)BH*Ss*HD];
__device__ __half g_Vh[(size_t)BH*Ss*HD];
__device__ float  g_HO[(size_t)Bb*Ss*Dd];             // head_out (B,S,H,hd)
__device__ float  g_scores[(size_t)NROWS*Ss];         // 512 MB
__device__ int2   g_ip[(size_t)NROWS*PAD];            // (idx, p-bits)
__device__ int    g_cnt[NROWS];

// ---------------------------------------------------------------------------
// packed f32x2 helpers
// ---------------------------------------------------------------------------
typedef unsigned long long u64t;

__device__ __forceinline__ u64t pack2(float x, float y) {
    u64t r;
    asm("mov.b64 %0, {%1, %2};" : "=l"(r) : "f"(x), "f"(y));
    return r;
}
__device__ __forceinline__ void fma2(u64t& d, u64t a, u64t b) {
    asm("fma.rn.f32x2 %0, %1, %2, %0;" : "+l"(d) : "l"(a), "l"(b));
}
__device__ __forceinline__ float2 unpack2(u64t v) {
    float2 f;
    asm("mov.b64 {%0, %1}, %2;" : "=f"(f.x), "=f"(f.y) : "l"(v));
    return f;
}

// ---------------------------------------------------------------------------
// shared 128x128x(K=1024) mainloop for the projection GEMMs
// ---------------------------------------------------------------------------
__device__ __forceinline__ void proj_mainloop(const float* __restrict__ A,
                                              const float* __restrict__ W,
                                              float (*As)[132], float (*Ws)[132],
                                              int m0, int n0, int tid,
                                              u64t acc[8][4])
{
    int tx = tid & 15, ty = tid >> 4;
#pragma unroll
    for (int i = 0; i < 8; i++)
#pragma unroll
        for (int j = 0; j < 4; j++) acc[i][j] = 0ull;

    for (int kt = 0; kt < Dd; kt += 32) {
#pragma unroll
        for (int l = 0; l < 4; l++) {
            int fid = tid + 256 * l;
            int lm = fid >> 3;
            int lk = (fid & 7) * 4;
            float4 av = *(const float4*)(A + (size_t)(m0 + lm) * Dd + kt + lk);
            As[lk+0][lm] = av.x; As[lk+1][lm] = av.y;
            As[lk+2][lm] = av.z; As[lk+3][lm] = av.w;
            float4 wv = *(const float4*)(W + (size_t)(n0 + lm) * Dd + kt + lk);
            Ws[lk+0][lm] = wv.x; Ws[lk+1][lm] = wv.y;
            Ws[lk+2][lm] = wv.z; Ws[lk+3][lm] = wv.w;
        }
        __syncthreads();
#pragma unroll
        for (int kk = 0; kk < 32; kk++) {
            float4 a0 = *(const float4*)&As[kk][ty*8];
            float4 a1 = *(const float4*)&As[kk][ty*8+4];
            ulonglong2 bq0 = *(const ulonglong2*)&Ws[kk][tx*8];
            ulonglong2 bq1 = *(const ulonglong2*)&Ws[kk][tx*8+4];
            u64t bp[4] = {bq0.x, bq0.y, bq1.x, bq1.y};
            float a[8] = {a0.x,a0.y,a0.z,a0.w,a1.x,a1.y,a1.z,a1.w};
#pragma unroll
            for (int i = 0; i < 8; i++) {
                u64t ai = pack2(a[i], a[i]);
#pragma unroll
                for (int j = 0; j < 4; j++) fma2(acc[i][j], ai, bp[j]);
            }
        }
        __syncthreads();
    }
}

// ---------------------------------------------------------------------------
// K1: fused QKV projection.  z = 0:Q  1:K  2:V(->half)
// ---------------------------------------------------------------------------
__global__ __launch_bounds__(256)
void qkv_kernel(const float* __restrict__ x,
                const float* __restrict__ Wq, const float* __restrict__ bq,
                const float* __restrict__ Wk, const float* __restrict__ bk,
                const float* __restrict__ Wv, const float* __restrict__ bv)
{
    __shared__ __align__(16) float As[32][132];
    __shared__ __align__(16) float Ws[32][132];

    int mode = blockIdx.z;
    const float* W    = (mode == 0) ? Wq : (mode == 1) ? Wk : Wv;
    const float* bias = (mode == 0) ? bq : (mode == 1) ? bk : bv;

    int n0 = blockIdx.x * 128;
    int m0 = blockIdx.y * 128;
    int tid = threadIdx.x;
    int tx = tid & 15, ty = tid >> 4;

    u64t acc[8][4];
    proj_mainloop(x, W, As, Ws, m0, n0, tid, acc);

    int nb = n0 + tx*8;
    float4 bs0 = *(const float4*)(bias + nb);
    float4 bs1 = *(const float4*)(bias + nb + 4);
    float bv8[8] = {bs0.x,bs0.y,bs0.z,bs0.w,bs1.x,bs1.y,bs1.z,bs1.w};

#pragma unroll
    for (int i = 0; i < 8; i++) {
        int m = m0 + ty*8 + i;
        float v[8];
#pragma unroll
        for (int j = 0; j < 4; j++) {
            float2 f = unpack2(acc[i][j]);
            v[2*j]   = f.x + bv8[2*j];
            v[2*j+1] = f.y + bv8[2*j+1];
        }
        int b = m >> 11, s = m & (Ss-1);
        int h = nb >> 6, d = nb & (HD-1);
        size_t off = (((size_t)(b*Hh + h)) * Ss + s) * HD + d;
        if (mode == 2) {
            __half2* p = (__half2*)g_Vh + (off >> 1);
            p[0] = __floats2half2_rn(v[0],v[1]);
            p[1] = __floats2half2_rn(v[2],v[3]);
            p[2] = __floats2half2_rn(v[4],v[5]);
            p[3] = __floats2half2_rn(v[6],v[7]);
        } else {
            float* dst = (mode == 0) ? g_Q : g_K;
            float4* p = (float4*)(dst + off);
            p[0] = make_float4(v[0],v[1],v[2],v[3]);
            p[1] = make_float4(v[4],v[5],v[6],v[7]);
        }
    }
}

// ---------------------------------------------------------------------------
// K6: output projection  out = g_HO @ Wo^T + bo
// ---------------------------------------------------------------------------
__global__ __launch_bounds__(256)
void oproj_kernel(const float* __restrict__ Wo, const float* __restrict__ bo,
                  float* __restrict__ Cext)
{
    __shared__ __align__(16) float As[32][132];
    __shared__ __align__(16) float Ws[32][132];

    int n0 = blockIdx.x * 128;
    int m0 = blockIdx.y * 128;
    int tid = threadIdx.x;
    int tx = tid & 15, ty = tid >> 4;

    u64t acc[8][4];
    proj_mainloop((const float*)g_HO, Wo, As, Ws, m0, n0, tid, acc);

    int nb = n0 + tx*8;
    float4 bs0 = *(const float4*)(bo + nb);
    float4 bs1 = *(const float4*)(bo + nb + 4);
    float bv8[8] = {bs0.x,bs0.y,bs0.z,bs0.w,bs1.x,bs1.y,bs1.z,bs1.w};

#pragma unroll
    for (int i = 0; i < 8; i++) {
        int m = m0 + ty*8 + i;
        float v[8];
#pragma unroll
        for (int j = 0; j < 4; j++) {
            float2 f = unpack2(acc[i][j]);
            v[2*j]   = f.x + bv8[2*j];
            v[2*j+1] = f.y + bv8[2*j+1];
        }
        float4* p = (float4*)(Cext + (size_t)m * Dd + nb);
        p[0] = make_float4(v[0],v[1],v[2],v[3]);
        p[1] = make_float4(v[4],v[5],v[6],v[7]);
    }
}

// ---------------------------------------------------------------------------
// K2: scores[bh,q,k] = (scale/temp[h]) * Q[bh,q,:]·K[bh,k,:]
// ---------------------------------------------------------------------------
__global__ __launch_bounds__(256)
void scores_kernel(const float* __restrict__ temperature)
{
    extern __shared__ __align__(16) float sm[];
    float (*Qs)[132] = (float(*)[132])sm;
    float (*Ks)[132] = (float(*)[132])(sm + 64*132);

    int bh = blockIdx.z;
    int h  = bh & (Hh-1);
    float t = temperature[h];
    t = (t < 0.1f) ? 0.1f : t;
    float sc = 0.125f / t;

    int q0 = blockIdx.y * 128;
    int k0 = blockIdx.x * 128;
    int tid = threadIdx.x;
    int tx = tid & 15, ty = tid >> 4;

    const float* Qb = g_Q + (size_t)bh * Ss * HD;
    const float* Kb = g_K + (size_t)bh * Ss * HD;

#pragma unroll
    for (int l = 0; l < 8; l++) {
        int fid = tid + 256 * l;
        int lm = fid >> 4;
        int lk = (fid & 15) * 4;
        float4 v = *(const float4*)(Qb + (size_t)(q0 + lm) * HD + lk);
        Qs[lk+0][lm] = v.x; Qs[lk+1][lm] = v.y; Qs[lk+2][lm] = v.z; Qs[lk+3][lm] = v.w;
        float4 w = *(const float4*)(Kb + (size_t)(k0 + lm) * HD + lk);
        Ks[lk+0][lm] = w.x; Ks[lk+1][lm] = w.y; Ks[lk+2][lm] = w.z; Ks[lk+3][lm] = w.w;
    }
    __syncthreads();

    u64t acc[8][4];
#pragma unroll
    for (int i = 0; i < 8; i++)
#pragma unroll
        for (int j = 0; j < 4; j++) acc[i][j] = 0ull;

#pragma unroll
    for (int kk = 0; kk < 64; kk++) {
        float4 a0 = *(const float4*)&Qs[kk][ty*8];
        float4 a1 = *(const float4*)&Qs[kk][ty*8+4];
        ulonglong2 bq0 = *(const ulonglong2*)&Ks[kk][tx*8];
        ulonglong2 bq1 = *(const ulonglong2*)&Ks[kk][tx*8+4];
        u64t bp[4] = {bq0.x, bq0.y, bq1.x, bq1.y};
        float a[8] = {a0.x,a0.y,a0.z,a0.w,a1.x,a1.y,a1.z,a1.w};
#pragma unroll
        for (int i = 0; i < 8; i++) {
            u64t ai = pack2(a[i], a[i]);
#pragma unroll
            for (int j = 0; j < 4; j++) fma2(acc[i][j], ai, bp[j]);
        }
    }

#pragma unroll
    for (int i = 0; i < 8; i++) {
        size_t rowoff = ((size_t)bh * Ss + (q0 + ty*8 + i)) * Ss + k0 + tx*8;
        float4* p = (float4*)(g_scores + rowoff);
        float2 f0 = unpack2(acc[i][0]);
        float2 f1 = unpack2(acc[i][1]);
        float2 f2 = unpack2(acc[i][2]);
        float2 f3 = unpack2(acc[i][3]);
        p[0] = make_float4(f0.x*sc, f0.y*sc, f1.x*sc, f1.y*sc);
        p[1] = make_float4(f2.x*sc, f2.y*sc, f3.x*sc, f3.y*sc);
    }
}

// ---------------------------------------------------------------------------
// K3: fused select + headout.
// Level-1 12-bit radix, then direct rank-scan among the (tiny) candidate set.
// ---------------------------------------------------------------------------
__device__ __forceinline__ float key_decode(unsigned uu) {
    unsigned b = (uu & 0x80000000u) ? (uu & 0x7FFFFFFFu) : ~uu;
    return __uint_as_float(b);
}
__device__ __forceinline__ unsigned hget(const unsigned* histw, int b) {
    return (histw[b >> 1] >> ((b & 1) * 16)) & 0xFFFFu;
}

template <int NBINS>
__device__ __forceinline__ void find_kth_p(const unsigned* histw, int k,
                                           unsigned* wtot,
                                           volatile int* s_bin, volatile int* s_rem)
{
    const int PER = NBINS / 256;
    int tid = threadIdx.x, lane = tid & 31, wp = tid >> 5;
    int base = NBINS - PER * (tid + 1);

    unsigned csum = 0;
    int wbase = base >> 1;
#pragma unroll
    for (int i = 0; i < PER/2; i++) {
        unsigned w = histw[wbase + i];
        csum += (w & 0xFFFFu) + (w >> 16);
    }
    unsigned inc = csum;
#pragma unroll
    for (int off = 1; off < 32; off <<= 1) {
        unsigned n = __shfl_up_sync(0xffffffffu, inc, off);
        if (lane >= off) inc += n;
    }
    if (lane == 31) wtot[wp] = inc;
    __syncthreads();
    unsigned woff = 0;
#pragma unroll
    for (int w = 0; w < 8; w++) woff += (w < wp) ? wtot[w] : 0u;
    inc += woff;
    unsigned pre = inc - csum;
    if (pre < (unsigned)k && (unsigned)k <= inc) {
        unsigned acc = pre;
        for (int b = base + PER - 1; b >= base; b--) {
            unsigned c = hget(histw, b);
            if (acc + c >= (unsigned)k) { *s_bin = b; *s_rem = k - (int)acc; break; }
            acc += c;
        }
    }
    __syncthreads();
}

__global__ __launch_bounds__(256)
void select_kernel()
{
    __shared__ unsigned u[Ss];            // 8KB keys
    __shared__ int2     sbuf[Ss];         // 16KB: cand/cand2 during radix, (i,e) after
    __shared__ unsigned histw[2048];      // 8KB; reused as gather reduction buffer
    __shared__ unsigned wtot[8];
    __shared__ float    wred[8];
    __shared__ int      s_bin, s_rem;
    __shared__ unsigned s_thr;
    __shared__ unsigned s_cand, s_cand2, s_out, s_umax;

    unsigned* cand  = (unsigned*)sbuf;         // 2048 entries
    unsigned* cand2 = (unsigned*)sbuf + 2048;  // 2048 entries

    int row = blockIdx.x;
    int tid = threadIdx.x;
    int lane = tid & 31;
    int wp = tid >> 5;
    unsigned lml = (1u << lane) - 1u;

    const float4* src4 = (const float4*)(g_scores + (size_t)row * Ss);

#pragma unroll
    for (int l = 0; l < 2; l++)
        ((uint4*)histw)[tid + 256*l] = make_uint4(0u, 0u, 0u, 0u);
    if (tid == 0) { s_cand = 0; s_cand2 = 0; s_out = 0; s_umax = 0; }
    __syncthreads();

    // sweep 1: load, keys, max, 12-bit packed histogram (direct atomics)
    unsigned umax = 0;
#pragma unroll
    for (int l = 0; l < 2; l++) {
        int i4 = tid + 256 * l;
        float4 v = src4[i4];
        float f[4] = {v.x, v.y, v.z, v.w};
#pragma unroll
        for (int c = 0; c < 4; c++) {
            unsigned bts = __float_as_uint(f[c]);
            unsigned uu = (bts & 0x80000000u) ? ~bts : (bts | 0x80000000u);
            u[i4*4 + c] = uu;
            umax = max(umax, uu);
            unsigned bin = uu >> 20;
            atomicAdd(&histw[bin >> 1], 1u << ((bin & 1) * 16));
        }
    }
#pragma unroll
    for (int off = 16; off; off >>= 1)
        umax = max(umax, __shfl_xor_sync(0xffffffffu, umax, off));
    if (lane == 0) atomicMax(&s_umax, umax);
    __syncthreads();

    // level 1: 12-bit
    find_kth_p<4096>(histw, KSEL, wtot, &s_bin, &s_rem);
    int bin1 = s_bin, rem1 = s_rem;

    // compact candidates with top-12 == bin1
#pragma unroll
    for (int l = 0; l < 8; l++) {
        unsigned uu = u[tid + 256*l];
        if ((uu >> 20) == (unsigned)bin1)
            cand[atomicAdd(&s_cand, 1u)] = uu;
    }
    __syncthreads();
    int c1 = (int)s_cand;

    unsigned thr;
    if (c1 <= 256) {
        // direct rank scan: rem1-th largest among c1 candidates (exact, with ties)
        if (tid < c1) {
            unsigned x = cand[tid];
            int ngt = 0, neq = 0;
            for (int j = 0; j < c1; j++) {
                unsigned y = cand[j];
                ngt += (y > x);
                neq += (y == x);
            }
            if (ngt < rem1 && ngt + neq >= rem1) s_thr = x;
        }
        __syncthreads();
        thr = s_thr;
    } else {
        // fallback: 10-bit level 2 + 10-bit level 3 (rare)
        if (tid < 256) { histw[tid] = 0; histw[tid + 256] = 0; }
        __syncthreads();
        for (int j = tid; j < c1; j += 256) {
            unsigned bin = (cand[j] >> 10) & 0x3FFu;
            atomicAdd(&histw[bin >> 1], 1u << ((bin & 1) * 16));
        }
        __syncthreads();
        find_kth_p<1024>(histw, rem1, wtot, &s_bin, &s_rem);
        int bin2 = s_bin, rem2 = s_rem;

        for (int j = tid; j < c1; j += 256) {
            unsigned uu = cand[j];
            if (((uu >> 10) & 0x3FFu) == (unsigned)bin2)
                cand2[atomicAdd(&s_cand2, 1u)] = uu;
        }
        __syncthreads();
        int c2 = (int)s_cand2;

        if (tid < 256) { histw[tid] = 0; histw[tid + 256] = 0; }
        __syncthreads();
        for (int j = tid; j < c2; j += 256) {
            unsigned bin = cand2[j] & 0x3FFu;
            atomicAdd(&histw[bin >> 1], 1u << ((bin & 1) * 16));
        }
        __syncthreads();
        find_kth_p<1024>(histw, rem2, wtot, &s_bin, &s_rem);
        thr = ((unsigned)bin1 << 20) | ((unsigned)bin2 << 10) | (unsigned)s_bin;
    }

    float mx = key_decode(s_umax);

    // fused pass: exp once, compact (i, e) into sbuf (ballot-aggregated)
    float lsum = 0.f;
#pragma unroll
    for (int l = 0; l < 8; l++) {
        int i = tid + 256*l;
        unsigned uu = u[i];
        bool p = (uu >= thr);
        float e = p ? __expf(key_decode(uu) - mx) : 0.f;
        lsum += e;
        unsigned m = __ballot_sync(0xffffffffu, p);
        if (p) {
            int leader = __ffs(m) - 1;
            unsigned base;
            if (lane == leader) base = atomicAdd(&s_out, (unsigned)__popc(m));
            base = __shfl_sync(m, base, leader);
            sbuf[base + __popc(m & lml)] = make_int2(i, __float_as_int(e));
        }
    }
#pragma unroll
    for (int off = 16; off; off >>= 1)
        lsum += __shfl_xor_sync(0xffffffffu, lsum, off);
    if (lane == 0) wred[wp] = lsum;
    __syncthreads();

    float tot = 0.f;
#pragma unroll
    for (int w = 0; w < 8; w++) tot += wred[w];
    float inv = 1.0f / tot;

    int cnt = (int)min(s_out, (unsigned)PAD);
    int2* gip = g_ip + (size_t)row * PAD;
    for (int j = tid; j < cnt; j += 256) {
        int2 e = sbuf[j];
        gip[j] = make_int2(e.x, __float_as_int(__int_as_float(e.y) * inv));
    }
    if (tid == 0) g_cnt[row] = cnt;

    // ---- fused headout: 2-way unrolled fp16 V gather ----
    {
        float (*pbuf)[64] = (float(*)[64])histw;   // 2KB, histw is dead
        int bh = row >> 11;
        const char* Vb = (const char*)(g_Vh + (size_t)bh * Ss * HD);
        int ksel = lane >> 3;
        int dgrp = lane & 7;

        float acc[8];
#pragma unroll
        for (int d = 0; d < 8; d++) acc[d] = 0.f;

        for (int j0 = wp * 8; j0 < cnt; j0 += 64) {
            int ja = j0 + ksel;
            int jb = ja + 4;
            int2 ea = (ja < cnt) ? sbuf[ja] : make_int2(0, 0);
            int2 eb = (jb < cnt) ? sbuf[jb] : make_int2(0, 0);
            float pa = __int_as_float(ea.y) * inv;
            float pb = __int_as_float(eb.y) * inv;
            uint4 va = *(const uint4*)(Vb + ((size_t)ea.x << 7) + (dgrp << 4));
            uint4 vb = *(const uint4*)(Vb + ((size_t)eb.x << 7) + (dgrp << 4));
            const __half2* ha = (const __half2*)&va;
            const __half2* hb = (const __half2*)&vb;
#pragma unroll
            for (int c = 0; c < 4; c++) {
                float2 fa = __half22float2(ha[c]);
                float2 fb = __half22float2(hb[c]);
                acc[2*c]   += pa * fa.x + pb * fb.x;
                acc[2*c+1] += pa * fa.y + pb * fb.y;
            }
        }

#pragma unroll
        for (int d = 0; d < 8; d++) {
            acc[d] += __shfl_xor_sync(0xffffffffu, acc[d], 8);
            acc[d] += __shfl_xor_sync(0xffffffffu, acc[d], 16);
        }
        if (lane < 8) {
#pragma unroll
            for (int d = 0; d < 8; d++) pbuf[wp][dgrp*8 + d] = acc[d];
        }
        __syncthreads();

        if (tid < 64) {
            float s = 0.f;
#pragma unroll
            for (int gg = 0; gg < 8; gg++) s += pbuf[gg][tid];
            int b = bh >> 4, h = bh & 15, sq = row & (Ss-1);
            g_HO[(((size_t)(b * Ss + sq)) * Hh + h) * HD + tid] = s;
        }
    }
}

// ---------------------------------------------------------------------------
// K5: avg_attention[b,q,:] = (1/H) * sum_h attn[b,h,q,:]
// ---------------------------------------------------------------------------
__global__ __launch_bounds__(256)
void avg_kernel(float* __restrict__ out_avg)
{
    __shared__ float acc[Ss];
    int bq = blockIdx.x;
    int b = bq >> 11, q = bq & (Ss-1);
    int tid = threadIdx.x;

    for (int i = tid; i < Ss; i += 256) acc[i] = 0.f;
    __syncthreads();

    const float invH = 1.0f / (float)Hh;
    for (int h = 0; h < Hh; h++) {
        int row = ((b * Hh + h) << 11) + q;
        int cnt = g_cnt[row];
        const int2* ip = g_ip + (size_t)row * PAD;
        for (int j = tid; j < cnt; j += 256) {
            int2 e = ip[j];
            atomicAdd(&acc[e.x], __int_as_float(e.y) * invH);
        }
    }
    __syncthreads();

    float* dst = out_avg + (size_t)bq * Ss;
    for (int i = tid; i < Ss; i += 256) dst[i] = acc[i];
}

// ---------------------------------------------------------------------------
extern "C" void kernel_launch(void* const* d_in, const int* in_sizes, int n_in,
                              void* d_out, int out_size)
{
    const float* x    = (const float*)d_in[0];
    const float* Wq   = (const float*)d_in[1];
    const float* bq   = (const float*)d_in[2];
    const float* Wk   = (const float*)d_in[3];
    const float* bk   = (const float*)d_in[4];
    const float* Wv   = (const float*)d_in[5];
    const float* bv   = (const float*)d_in[6];
    const float* Wo   = (const float*)d_in[7];
    const float* bo   = (const float*)d_in[8];
    const float* temp = (const float*)d_in[9];

    float* out     = (float*)d_out;
    float* out_avg = out + (size_t)Bb * Ss * Dd;

    static cudaStream_t s2 = nullptr;
    static cudaEvent_t ev_fork = nullptr, ev_join = nullptr;
    if (s2 == nullptr) {
        cudaStreamCreateWithFlags(&s2, cudaStreamNonBlocking);
        cudaEventCreateWithFlags(&ev_fork, cudaEventDisableTiming);
        cudaEventCreateWithFlags(&ev_join, cudaEventDisableTiming);
        cudaFuncSetAttribute(scores_kernel,
                             cudaFuncAttributeMaxDynamicSharedMemorySize,
                             2 * 64 * 132 * 4);
    }

    dim3 gqkv(Dd / 128, (Bb * Ss) / 128, 3);      // (8, 32, 3)
    qkv_kernel<<<gqkv, 256>>>(x, Wq, bq, Wk, bk, Wv, bv);

    dim3 gsc(Ss / 128, Ss / 128, BH);             // (16, 16, 32)
    scores_kernel<<<gsc, 256, 2 * 64 * 132 * 4>>>(temp);

    select_kernel<<<NROWS, 256>>>();              // select + headout fused

    // fork: avg on side stream, overlapped with oproj on the main stream
    cudaEventRecord(ev_fork, 0);
    cudaStreamWaitEvent(s2, ev_fork, 0);
    avg_kernel<<<Bb * Ss, 256, 0, s2>>>(out_avg);
    cudaEventRecord(ev_join, s2);

    dim3 gproj(Dd / 128, (Bb * Ss) / 128);        // (8, 32)
    oproj_kernel<<<gproj, 256>>>(Wo, bo, out);

    cudaStreamWaitEvent(0, ev_join, 0);           // join before returning
}

// round 16
// speedup vs baseline: 1.1273x; 1.0825x over previous
#include <cuda_runtime.h>
#include <cuda_fp16.h>
#include <cstdint>

// ---------------------------------------------------------------------------
// SparseMultiHeadAttention  B=2 S=2048 D=1024 H=16 hd=64  top-k k=409
// R15: R14 base + scores via 3xTF32 mma.sync (fp32-grade precision)
// ---------------------------------------------------------------------------

#define Bb   2
#define Ss   2048
#define Dd   1024
#define Hh   16
#define HD   64
#define BH   (Bb*Hh)          // 32
#define NROWS (Bb*Hh*Ss)      // 65536
#define KSEL 409
#define PAD  512

// scratch (device globals: allocation-free)
__device__ float  g_Q[(size_t)BH*Ss*HD];
__device__ float  g_K[(size_t)BH*Ss*HD];
__device__ __half g_Vh[(size_t)BH*Ss*HD];
__device__ float  g_HO[(size_t)Bb*Ss*Dd];             // head_out (B,S,H,hd)
__device__ float  g_scores[(size_t)NROWS*Ss];         // 512 MB
__device__ int2   g_ip[(size_t)NROWS*PAD];            // (idx, p-bits)
__device__ int    g_cnt[NROWS];

// ---------------------------------------------------------------------------
// packed f32x2 helpers
// ---------------------------------------------------------------------------
typedef unsigned long long u64t;

__device__ __forceinline__ u64t pack2(float x, float y) {
    u64t r;
    asm("mov.b64 %0, {%1, %2};" : "=l"(r) : "f"(x), "f"(y));
    return r;
}
__device__ __forceinline__ void fma2(u64t& d, u64t a, u64t b) {
    asm("fma.rn.f32x2 %0, %1, %2, %0;" : "+l"(d) : "l"(a), "l"(b));
}
__device__ __forceinline__ float2 unpack2(u64t v) {
    float2 f;
    asm("mov.b64 {%0, %1}, %2;" : "=f"(f.x), "=f"(f.y) : "l"(v));
    return f;
}

// ---------------------------------------------------------------------------
// tf32 helpers (mma.sync is base-family PTX, unlike tcgen05)
// ---------------------------------------------------------------------------
__device__ __forceinline__ void tf32split(float x, uint32_t& hi, uint32_t& lo) {
    asm("cvt.rna.tf32.f32 %0, %1;" : "=r"(hi) : "f"(x));
    float r = x - __uint_as_float(hi);
    asm("cvt.rna.tf32.f32 %0, %1;" : "=r"(lo) : "f"(r));
}
__device__ __forceinline__ void mma_tf32(float (&d)[4], const uint32_t* a,
                                         const uint32_t* b) {
    asm("mma.sync.aligned.m16n8k8.row.col.f32.tf32.tf32.f32 "
        "{%0,%1,%2,%3}, {%4,%5,%6,%7}, {%8,%9}, {%0,%1,%2,%3};"
        : "+f"(d[0]), "+f"(d[1]), "+f"(d[2]), "+f"(d[3])
        : "r"(a[0]), "r"(a[1]), "r"(a[2]), "r"(a[3]), "r"(b[0]), "r"(b[1]));
}

// ---------------------------------------------------------------------------
// shared 128x128x(K=1024) mainloop for the projection GEMMs
// ---------------------------------------------------------------------------
__device__ __forceinline__ void proj_mainloop(const float* __restrict__ A,
                                              const float* __restrict__ W,
                                              float (*As)[132], float (*Ws)[132],
                                              int m0, int n0, int tid,
                                              u64t acc[8][4])
{
    int tx = tid & 15, ty = tid >> 4;
#pragma unroll
    for (int i = 0; i < 8; i++)
#pragma unroll
        for (int j = 0; j < 4; j++) acc[i][j] = 0ull;

    for (int kt = 0; kt < Dd; kt += 32) {
#pragma unroll
        for (int l = 0; l < 4; l++) {
            int fid = tid + 256 * l;
            int lm = fid >> 3;
            int lk = (fid & 7) * 4;
            float4 av = *(const float4*)(A + (size_t)(m0 + lm) * Dd + kt + lk);
            As[lk+0][lm] = av.x; As[lk+1][lm] = av.y;
            As[lk+2][lm] = av.z; As[lk+3][lm] = av.w;
            float4 wv = *(const float4*)(W + (size_t)(n0 + lm) * Dd + kt + lk);
            Ws[lk+0][lm] = wv.x; Ws[lk+1][lm] = wv.y;
            Ws[lk+2][lm] = wv.z; Ws[lk+3][lm] = wv.w;
        }
        __syncthreads();
#pragma unroll
        for (int kk = 0; kk < 32; kk++) {
            float4 a0 = *(const float4*)&As[kk][ty*8];
            float4 a1 = *(const float4*)&As[kk][ty*8+4];
            ulonglong2 bq0 = *(const ulonglong2*)&Ws[kk][tx*8];
            ulonglong2 bq1 = *(const ulonglong2*)&Ws[kk][tx*8+4];
            u64t bp[4] = {bq0.x, bq0.y, bq1.x, bq1.y};
            float a[8] = {a0.x,a0.y,a0.z,a0.w,a1.x,a1.y,a1.z,a1.w};
#pragma unroll
            for (int i = 0; i < 8; i++) {
                u64t ai = pack2(a[i], a[i]);
#pragma unroll
                for (int j = 0; j < 4; j++) fma2(acc[i][j], ai, bp[j]);
            }
        }
        __syncthreads();
    }
}

// ---------------------------------------------------------------------------
// K1: fused QKV projection.  z = 0:Q  1:K  2:V(->half)
// ---------------------------------------------------------------------------
__global__ __launch_bounds__(256)
void qkv_kernel(const float* __restrict__ x,
                const float* __restrict__ Wq, const float* __restrict__ bq,
                const float* __restrict__ Wk, const float* __restrict__ bk,
                const float* __restrict__ Wv, const float* __restrict__ bv)
{
    __shared__ __align__(16) float As[32][132];
    __shared__ __align__(16) float Ws[32][132];

    int mode = blockIdx.z;
    const float* W    = (mode == 0) ? Wq : (mode == 1) ? Wk : Wv;
    const float* bias = (mode == 0) ? bq : (mode == 1) ? bk : bv;

    int n0 = blockIdx.x * 128;
    int m0 = blockIdx.y * 128;
    int tid = threadIdx.x;
    int tx = tid & 15, ty = tid >> 4;

    u64t acc[8][4];
    proj_mainloop(x, W, As, Ws, m0, n0, tid, acc);

    int nb = n0 + tx*8;
    float4 bs0 = *(const float4*)(bias + nb);
    float4 bs1 = *(const float4*)(bias + nb + 4);
    float bv8[8] = {bs0.x,bs0.y,bs0.z,bs0.w,bs1.x,bs1.y,bs1.z,bs1.w};

#pragma unroll
    for (int i = 0; i < 8; i++) {
        int m = m0 + ty*8 + i;
        float v[8];
#pragma unroll
        for (int j = 0; j < 4; j++) {
            float2 f = unpack2(acc[i][j]);
            v[2*j]   = f.x + bv8[2*j];
            v[2*j+1] = f.y + bv8[2*j+1];
        }
        int b = m >> 11, s = m & (Ss-1);
        int h = nb >> 6, d = nb & (HD-1);
        size_t off = (((size_t)(b*Hh + h)) * Ss + s) * HD + d;
        if (mode == 2) {
            __half2* p = (__half2*)g_Vh + (off >> 1);
            p[0] = __floats2half2_rn(v[0],v[1]);
            p[1] = __floats2half2_rn(v[2],v[3]);
            p[2] = __floats2half2_rn(v[4],v[5]);
            p[3] = __floats2half2_rn(v[6],v[7]);
        } else {
            float* dst = (mode == 0) ? g_Q : g_K;
            float4* p = (float4*)(dst + off);
            p[0] = make_float4(v[0],v[1],v[2],v[3]);
            p[1] = make_float4(v[4],v[5],v[6],v[7]);
        }
    }
}

// ---------------------------------------------------------------------------
// K6: output projection  out = g_HO @ Wo^T + bo
// ---------------------------------------------------------------------------
__global__ __launch_bounds__(256)
void oproj_kernel(const float* __restrict__ Wo, const float* __restrict__ bo,
                  float* __restrict__ Cext)
{
    __shared__ __align__(16) float As[32][132];
    __shared__ __align__(16) float Ws[32][132];

    int n0 = blockIdx.x * 128;
    int m0 = blockIdx.y * 128;
    int tid = threadIdx.x;
    int tx = tid & 15, ty = tid >> 4;

    u64t acc[8][4];
    proj_mainloop((const float*)g_HO, Wo, As, Ws, m0, n0, tid, acc);

    int nb = n0 + tx*8;
    float4 bs0 = *(const float4*)(bo + nb);
    float4 bs1 = *(const float4*)(bo + nb + 4);
    float bv8[8] = {bs0.x,bs0.y,bs0.z,bs0.w,bs1.x,bs1.y,bs1.z,bs1.w};

#pragma unroll
    for (int i = 0; i < 8; i++) {
        int m = m0 + ty*8 + i;
        float v[8];
#pragma unroll
        for (int j = 0; j < 4; j++) {
            float2 f = unpack2(acc[i][j]);
            v[2*j]   = f.x + bv8[2*j];
            v[2*j+1] = f.y + bv8[2*j+1];
        }
        float4* p = (float4*)(Cext + (size_t)m * Dd + nb);
        p[0] = make_float4(v[0],v[1],v[2],v[3]);
        p[1] = make_float4(v[4],v[5],v[6],v[7]);
    }
}

// ---------------------------------------------------------------------------
// K2: scores via 3xTF32 mma.sync.m16n8k8
// CTA 128(q)x128(k), 8 warps 2x4 (warp tile 64x32), K=64.
// ---------------------------------------------------------------------------
#define SC_LD   68
#define SC_SMEM (2 * 128 * SC_LD * 4)   // 69632 B

__global__ __launch_bounds__(256)
void scores_kernel(const float* __restrict__ temperature)
{
    extern __shared__ __align__(16) float sm[];
    float* Qs = sm;                    // [128][SC_LD], row-major (q, k)
    float* Ks = sm + 128 * SC_LD;      // [128][SC_LD], row-major (kpos, k)

    int bh = blockIdx.z;
    int h  = bh & (Hh-1);
    float t = temperature[h];
    t = (t < 0.1f) ? 0.1f : t;
    float sc = 0.125f / t;

    int q0 = blockIdx.y * 128;
    int k0 = blockIdx.x * 128;
    int tid = threadIdx.x;
    int lane = tid & 31, wp = tid >> 5;

    const float* Qb = g_Q + (size_t)bh * Ss * HD;
    const float* Kb = g_K + (size_t)bh * Ss * HD;

#pragma unroll
    for (int l = 0; l < 8; l++) {
        int fid = tid + 256 * l;           // 0..2047
        int lm = fid >> 4;                 // 0..127
        int lk = (fid & 15) * 4;           // 0..60
        *(float4*)(Qs + lm * SC_LD + lk) =
            *(const float4*)(Qb + (size_t)(q0 + lm) * HD + lk);
        *(float4*)(Ks + lm * SC_LD + lk) =
            *(const float4*)(Kb + (size_t)(k0 + lm) * HD + lk);
    }
    __syncthreads();

    int m_base = (wp & 1) * 64;            // warp rows: 64
    int n_base = (wp >> 1) * 32;           // warp cols: 32
    int g  = lane >> 2;                    // 0..7
    int tg = lane & 3;                     // 0..3

    float acc[4][4][4];
#pragma unroll
    for (int mt = 0; mt < 4; mt++)
#pragma unroll
        for (int nt = 0; nt < 4; nt++)
#pragma unroll
            for (int c = 0; c < 4; c++) acc[mt][nt][c] = 0.f;

#pragma unroll
    for (int ks = 0; ks < 8; ks++) {
        int kk = ks * 8;
        uint32_t ahi[4][4], alo[4][4];
#pragma unroll
        for (int mt = 0; mt < 4; mt++) {
            const float* r0 = Qs + (m_base + mt*16 + g) * SC_LD + kk;
            const float* r1 = r0 + 8 * SC_LD;
            tf32split(r0[tg],     ahi[mt][0], alo[mt][0]);
            tf32split(r1[tg],     ahi[mt][1], alo[mt][1]);
            tf32split(r0[tg + 4], ahi[mt][2], alo[mt][2]);
            tf32split(r1[tg + 4], ahi[mt][3], alo[mt][3]);
        }
        uint32_t bhi[4][2], blo[4][2];
#pragma unroll
        for (int nt = 0; nt < 4; nt++) {
            const float* c0 = Ks + (n_base + nt*8 + g) * SC_LD + kk;
            tf32split(c0[tg],     bhi[nt][0], blo[nt][0]);
            tf32split(c0[tg + 4], bhi[nt][1], blo[nt][1]);
        }
#pragma unroll
        for (int mt = 0; mt < 4; mt++)
#pragma unroll
            for (int nt = 0; nt < 4; nt++) {
                mma_tf32(acc[mt][nt], ahi[mt], blo[nt]);
                mma_tf32(acc[mt][nt], alo[mt], bhi[nt]);
                mma_tf32(acc[mt][nt], ahi[mt], bhi[nt]);
            }
    }

    // epilogue: c0,c1 -> (row g, cols 2tg,2tg+1); c2,c3 -> row g+8
#pragma unroll
    for (int mt = 0; mt < 4; mt++) {
        int r0 = q0 + m_base + mt*16 + g;
        size_t ro0 = ((size_t)bh * Ss + r0) * Ss;
        size_t ro1 = ((size_t)bh * Ss + r0 + 8) * Ss;
#pragma unroll
        for (int nt = 0; nt < 4; nt++) {
            int cc = k0 + n_base + nt*8 + 2*tg;
            *(float2*)(g_scores + ro0 + cc) =
                make_float2(acc[mt][nt][0] * sc, acc[mt][nt][1] * sc);
            *(float2*)(g_scores + ro1 + cc) =
                make_float2(acc[mt][nt][2] * sc, acc[mt][nt][3] * sc);
        }
    }
}

// ---------------------------------------------------------------------------
// K3: fused select + headout (R14 version).
// ---------------------------------------------------------------------------
__device__ __forceinline__ float key_decode(unsigned uu) {
    unsigned b = (uu & 0x80000000u) ? (uu & 0x7FFFFFFFu) : ~uu;
    return __uint_as_float(b);
}
__device__ __forceinline__ unsigned hget(const unsigned* histw, int b) {
    return (histw[b >> 1] >> ((b & 1) * 16)) & 0xFFFFu;
}

template <int NBINS>
__device__ __forceinline__ void find_kth_p(const unsigned* histw, int k,
                                           unsigned* wtot,
                                           volatile int* s_bin, volatile int* s_rem)
{
    const int PER = NBINS / 256;
    int tid = threadIdx.x, lane = tid & 31, wp = tid >> 5;
    int base = NBINS - PER * (tid + 1);

    unsigned csum = 0;
    int wbase = base >> 1;
#pragma unroll
    for (int i = 0; i < PER/2; i++) {
        unsigned w = histw[wbase + i];
        csum += (w & 0xFFFFu) + (w >> 16);
    }
    unsigned inc = csum;
#pragma unroll
    for (int off = 1; off < 32; off <<= 1) {
        unsigned n = __shfl_up_sync(0xffffffffu, inc, off);
        if (lane >= off) inc += n;
    }
    if (lane == 31) wtot[wp] = inc;
    __syncthreads();
    unsigned woff = 0;
#pragma unroll
    for (int w = 0; w < 8; w++) woff += (w < wp) ? wtot[w] : 0u;
    inc += woff;
    unsigned pre = inc - csum;
    if (pre < (unsigned)k && (unsigned)k <= inc) {
        unsigned acc = pre;
        for (int b = base + PER - 1; b >= base; b--) {
            unsigned c = hget(histw, b);
            if (acc + c >= (unsigned)k) { *s_bin = b; *s_rem = k - (int)acc; break; }
            acc += c;
        }
    }
    __syncthreads();
}

__global__ __launch_bounds__(256)
void select_kernel()
{
    __shared__ unsigned u[Ss];
    __shared__ int2     sbuf[Ss];
    __shared__ unsigned histw[2048];
    __shared__ unsigned wtot[8];
    __shared__ float    wred[8];
    __shared__ int      s_bin, s_rem;
    __shared__ unsigned s_thr;
    __shared__ unsigned s_cand, s_cand2, s_out, s_umax;

    unsigned* cand  = (unsigned*)sbuf;
    unsigned* cand2 = (unsigned*)sbuf + 2048;

    int row = blockIdx.x;
    int tid = threadIdx.x;
    int lane = tid & 31;
    int wp = tid >> 5;
    unsigned lml = (1u << lane) - 1u;

    const float4* src4 = (const float4*)(g_scores + (size_t)row * Ss);

#pragma unroll
    for (int l = 0; l < 2; l++)
        ((uint4*)histw)[tid + 256*l] = make_uint4(0u, 0u, 0u, 0u);
    if (tid == 0) { s_cand = 0; s_cand2 = 0; s_out = 0; s_umax = 0; }
    __syncthreads();

    unsigned umax = 0;
#pragma unroll
    for (int l = 0; l < 2; l++) {
        int i4 = tid + 256 * l;
        float4 v = src4[i4];
        float f[4] = {v.x, v.y, v.z, v.w};
#pragma unroll
        for (int c = 0; c < 4; c++) {
            unsigned bts = __float_as_uint(f[c]);
            unsigned uu = (bts & 0x80000000u) ? ~bts : (bts | 0x80000000u);
            u[i4*4 + c] = uu;
            umax = max(umax, uu);
            unsigned bin = uu >> 20;
            atomicAdd(&histw[bin >> 1], 1u << ((bin & 1) * 16));
        }
    }
#pragma unroll
    for (int off = 16; off; off >>= 1)
        umax = max(umax, __shfl_xor_sync(0xffffffffu, umax, off));
    if (lane == 0) atomicMax(&s_umax, umax);
    __syncthreads();

    find_kth_p<4096>(histw, KSEL, wtot, &s_bin, &s_rem);
    int bin1 = s_bin, rem1 = s_rem;

#pragma unroll
    for (int l = 0; l < 8; l++) {
        unsigned uu = u[tid + 256*l];
        if ((uu >> 20) == (unsigned)bin1)
            cand[atomicAdd(&s_cand, 1u)] = uu;
    }
    __syncthreads();
    int c1 = (int)s_cand;

    unsigned thr;
    if (c1 <= 256) {
        if (tid < c1) {
            unsigned x = cand[tid];
            int ngt = 0, neq = 0;
            for (int j = 0; j < c1; j++) {
                unsigned y = cand[j];
                ngt += (y > x);
                neq += (y == x);
            }
            if (ngt < rem1 && ngt + neq >= rem1) s_thr = x;
        }
        __syncthreads();
        thr = s_thr;
    } else {
        if (tid < 256) { histw[tid] = 0; histw[tid + 256] = 0; }
        __syncthreads();
        for (int j = tid; j < c1; j += 256) {
            unsigned bin = (cand[j] >> 10) & 0x3FFu;
            atomicAdd(&histw[bin >> 1], 1u << ((bin & 1) * 16));
        }
        __syncthreads();
        find_kth_p<1024>(histw, rem1, wtot, &s_bin, &s_rem);
        int bin2 = s_bin, rem2 = s_rem;

        for (int j = tid; j < c1; j += 256) {
            unsigned uu = cand[j];
            if (((uu >> 10) & 0x3FFu) == (unsigned)bin2)
                cand2[atomicAdd(&s_cand2, 1u)] = uu;
        }
        __syncthreads();
        int c2 = (int)s_cand2;

        if (tid < 256) { histw[tid] = 0; histw[tid + 256] = 0; }
        __syncthreads();
        for (int j = tid; j < c2; j += 256) {
            unsigned bin = cand2[j] & 0x3FFu;
            atomicAdd(&histw[bin >> 1], 1u << ((bin & 1) * 16));
        }
        __syncthreads();
        find_kth_p<1024>(histw, rem2, wtot, &s_bin, &s_rem);
        thr = ((unsigned)bin1 << 20) | ((unsigned)bin2 << 10) | (unsigned)s_bin;
    }

    float mx = key_decode(s_umax);

    float lsum = 0.f;
#pragma unroll
    for (int l = 0; l < 8; l++) {
        int i = tid + 256*l;
        unsigned uu = u[i];
        bool p = (uu >= thr);
        float e = p ? __expf(key_decode(uu) - mx) : 0.f;
        lsum += e;
        unsigned m = __ballot_sync(0xffffffffu, p);
        if (p) {
            int leader = __ffs(m) - 1;
            unsigned base;
            if (lane == leader) base = atomicAdd(&s_out, (unsigned)__popc(m));
            base = __shfl_sync(m, base, leader);
            sbuf[base + __popc(m & lml)] = make_int2(i, __float_as_int(e));
        }
    }
#pragma unroll
    for (int off = 16; off; off >>= 1)
        lsum += __shfl_xor_sync(0xffffffffu, lsum, off);
    if (lane == 0) wred[wp] = lsum;
    __syncthreads();

    float tot = 0.f;
#pragma unroll
    for (int w = 0; w < 8; w++) tot += wred[w];
    float inv = 1.0f / tot;

    int cnt = (int)min(s_out, (unsigned)PAD);
    int2* gip = g_ip + (size_t)row * PAD;
    for (int j = tid; j < cnt; j += 256) {
        int2 e = sbuf[j];
        gip[j] = make_int2(e.x, __float_as_int(__int_as_float(e.y) * inv));
    }
    if (tid == 0) g_cnt[row] = cnt;

    // fused headout: 2-way unrolled fp16 V gather
    {
        float (*pbuf)[64] = (float(*)[64])histw;
        int bh = row >> 11;
        const char* Vb = (const char*)(g_Vh + (size_t)bh * Ss * HD);
        int ksel = lane >> 3;
        int dgrp = lane & 7;

        float acc[8];
#pragma unroll
        for (int d = 0; d < 8; d++) acc[d] = 0.f;

        for (int j0 = wp * 8; j0 < cnt; j0 += 64) {
            int ja = j0 + ksel;
            int jb = ja + 4;
            int2 ea = (ja < cnt) ? sbuf[ja] : make_int2(0, 0);
            int2 eb = (jb < cnt) ? sbuf[jb] : make_int2(0, 0);
            float pa = __int_as_float(ea.y) * inv;
            float pb = __int_as_float(eb.y) * inv;
            uint4 va = *(const uint4*)(Vb + ((size_t)ea.x << 7) + (dgrp << 4));
            uint4 vb = *(const uint4*)(Vb + ((size_t)eb.x << 7) + (dgrp << 4));
            const __half2* ha = (const __half2*)&va;
            const __half2* hb = (const __half2*)&vb;
#pragma unroll
            for (int c = 0; c < 4; c++) {
                float2 fa = __half22float2(ha[c]);
                float2 fb = __half22float2(hb[c]);
                acc[2*c]   += pa * fa.x + pb * fb.x;
                acc[2*c+1] += pa * fa.y + pb * fb.y;
            }
        }

#pragma unroll
        for (int d = 0; d < 8; d++) {
            acc[d] += __shfl_xor_sync(0xffffffffu, acc[d], 8);
            acc[d] += __shfl_xor_sync(0xffffffffu, acc[d], 16);
        }
        if (lane < 8) {
#pragma unroll
            for (int d = 0; d < 8; d++) pbuf[wp][dgrp*8 + d] = acc[d];
        }
        __syncthreads();

        if (tid < 64) {
            float s = 0.f;
#pragma unroll
            for (int gg = 0; gg < 8; gg++) s += pbuf[gg][tid];
            int b = bh >> 4, h = bh & 15, sq = row & (Ss-1);
            g_HO[(((size_t)(b * Ss + sq)) * Hh + h) * HD + tid] = s;
        }
    }
}

// ---------------------------------------------------------------------------
// K5: avg_attention[b,q,:] = (1/H) * sum_h attn[b,h,q,:]
// ---------------------------------------------------------------------------
__global__ __launch_bounds__(256)
void avg_kernel(float* __restrict__ out_avg)
{
    __shared__ float acc[Ss];
    int bq = blockIdx.x;
    int b = bq >> 11, q = bq & (Ss-1);
    int tid = threadIdx.x;

    for (int i = tid; i < Ss; i += 256) acc[i] = 0.f;
    __syncthreads();

    const float invH = 1.0f / (float)Hh;
    for (int h = 0; h < Hh; h++) {
        int row = ((b * Hh + h) << 11) + q;
        int cnt = g_cnt[row];
        const int2* ip = g_ip + (size_t)row * PAD;
        for (int j = tid; j < cnt; j += 256) {
            int2 e = ip[j];
            atomicAdd(&acc[e.x], __int_as_float(e.y) * invH);
        }
    }
    __syncthreads();

    float* dst = out_avg + (size_t)bq * Ss;
    for (int i = tid; i < Ss; i += 256) dst[i] = acc[i];
}

// ---------------------------------------------------------------------------
extern "C" void kernel_launch(void* const* d_in, const int* in_sizes, int n_in,
                              void* d_out, int out_size)
{
    const float* x    = (const float*)d_in[0];
    const float* Wq   = (const float*)d_in[1];
    const float* bq   = (const float*)d_in[2];
    const float* Wk   = (const float*)d_in[3];
    const float* bk   = (const float*)d_in[4];
    const float* Wv   = (const float*)d_in[5];
    const float* bv   = (const float*)d_in[6];
    const float* Wo   = (const float*)d_in[7];
    const float* bo   = (const float*)d_in[8];
    const float* temp = (const float*)d_in[9];

    float* out     = (float*)d_out;
    float* out_avg = out + (size_t)Bb * Ss * Dd;

    static cudaStream_t s2 = nullptr;
    static cudaEvent_t ev_fork = nullptr, ev_join = nullptr;
    if (s2 == nullptr) {
        cudaStreamCreateWithFlags(&s2, cudaStreamNonBlocking);
        cudaEventCreateWithFlags(&ev_fork, cudaEventDisableTiming);
        cudaEventCreateWithFlags(&ev_join, cudaEventDisableTiming);
        cudaFuncSetAttribute(scores_kernel,
                             cudaFuncAttributeMaxDynamicSharedMemorySize,
                             SC_SMEM);
    }

    dim3 gqkv(Dd / 128, (Bb * Ss) / 128, 3);      // (8, 32, 3)
    qkv_kernel<<<gqkv, 256>>>(x, Wq, bq, Wk, bk, Wv, bv);

    dim3 gsc(Ss / 128, Ss / 128, BH);             // (16, 16, 32)
    scores_kernel<<<gsc, 256, SC_SMEM>>>(temp);

    select_kernel<<<NROWS, 256>>>();              // select + headout fused

    // fork: avg on side stream, overlapped with oproj on the main stream
    cudaEventRecord(ev_fork, 0);
    cudaStreamWaitEvent(s2, ev_fork, 0);
    avg_kernel<<<Bb * Ss, 256, 0, s2>>>(out_avg);
    cudaEventRecord(ev_join, s2);

    dim3 gproj(Dd / 128, (Bb * Ss) / 128);        // (8, 32)
    oproj_kernel<<<gproj, 256>>>(Wo, bo, out);

    cudaStreamWaitEvent(0, ev_join, 0);           // join before returning
}